// round 14
// baseline (speedup 1.0000x reference)
#include <cuda_runtime.h>
#include <cuda_bf16.h>
#include <cstdint>
#include <cstddef>

#define BB    8
#define CIN   768
#define LSEQ  4096
#define CH    96
#define COUTC 768

// ---- device-global scratch ----
__device__ signed char   g_Q8h[BB * LSEQ * CH], g_Q8l[BB * LSEQ * CH];
__device__ signed char   g_K8h[BB * LSEQ * CH], g_K8l[BB * LSEQ * CH];
__device__ __nv_bfloat16 g_Vh[BB * LSEQ * CH],  g_Vl[BB * LSEQ * CH];
__device__ __nv_bfloat16 g_Oh[BB * LSEQ * CH],  g_Ol[BB * LSEQ * CH];
__device__ __nv_bfloat16 g_Wh[COUTC * CH],      g_Wl[COUTC * CH];
__device__ __nv_bfloat16 g_Wqh[CH * CIN], g_Wql[CH * CIN];
__device__ __nv_bfloat16 g_Wkh[CH * CIN], g_Wkl[CH * CIN];
__device__ __nv_bfloat16 g_Wvh[CH * CIN], g_Wvl[CH * CIN];

// quant constants: scale 8/127, residual scale (8/127)/128
#define QSCL  15.875f            // 127/8
#define QINV  0.06299212598f     // 8/127
#define QRES  2032.0f            // 127*128/8
#define SQ2   3.96800794e-3f     // (8/127)^2
#define SQ2R  3.10000620e-5f     // SQ2/128

// ============================================================================
// PTX helpers
// ============================================================================
__device__ __forceinline__ uint32_t s2u(const void* p) {
    return (uint32_t)__cvta_generic_to_shared(p);
}
__device__ __forceinline__ void ldsm4(uint32_t r[4], uint32_t a) {
    asm volatile("ldmatrix.sync.aligned.m8n8.x4.shared.b16 {%0,%1,%2,%3}, [%4];"
                 : "=r"(r[0]), "=r"(r[1]), "=r"(r[2]), "=r"(r[3]) : "r"(a));
}
__device__ __forceinline__ void ldsm4t(uint32_t r[4], uint32_t a) {
    asm volatile("ldmatrix.sync.aligned.m8n8.x4.trans.shared.b16 {%0,%1,%2,%3}, [%4];"
                 : "=r"(r[0]), "=r"(r[1]), "=r"(r[2]), "=r"(r[3]) : "r"(a));
}
__device__ __forceinline__ void ldsm2(uint32_t r[2], uint32_t a) {
    asm volatile("ldmatrix.sync.aligned.m8n8.x2.shared.b16 {%0,%1}, [%2];"
                 : "=r"(r[0]), "=r"(r[1]) : "r"(a));
}
__device__ __forceinline__ void mma_bf16(float d[4], const uint32_t a[4], const uint32_t b[2]) {
    asm volatile("mma.sync.aligned.m16n8k16.row.col.f32.bf16.bf16.f32 "
                 "{%0,%1,%2,%3}, {%4,%5,%6,%7}, {%8,%9}, {%0,%1,%2,%3};"
                 : "+f"(d[0]), "+f"(d[1]), "+f"(d[2]), "+f"(d[3])
                 : "r"(a[0]), "r"(a[1]), "r"(a[2]), "r"(a[3]), "r"(b[0]), "r"(b[1]));
}
__device__ __forceinline__ void mma_s8(int d[4], const uint32_t a[4], const uint32_t b[2]) {
    asm volatile("mma.sync.aligned.m16n8k32.row.col.s32.s8.s8.s32 "
                 "{%0,%1,%2,%3}, {%4,%5,%6,%7}, {%8,%9}, {%0,%1,%2,%3};"
                 : "+r"(d[0]), "+r"(d[1]), "+r"(d[2]), "+r"(d[3])
                 : "r"(a[0]), "r"(a[1]), "r"(a[2]), "r"(a[3]), "r"(b[0]), "r"(b[1]));
}
__device__ __forceinline__ void cpa16(uint32_t dst, const void* src) {
    asm volatile("cp.async.cg.shared.global [%0], [%1], 16;" :: "r"(dst), "l"(src));
}
#define CP_COMMIT() asm volatile("cp.async.commit_group;" ::: "memory")
#define CP_WAIT0()  asm volatile("cp.async.wait_group 0;" ::: "memory")
#define CP_WAIT1()  asm volatile("cp.async.wait_group 1;" ::: "memory")

__device__ __forceinline__ void split4(__nv_bfloat16* hiB, __nv_bfloat16* loB,
                                       int eoff, float4 v) {
    float f[4] = {v.x, v.y, v.z, v.w};
    unsigned short h[4], l[4];
#pragma unroll
    for (int i = 0; i < 4; ++i) {
        __nv_bfloat16 hb = __float2bfloat16(f[i]);
        float r = f[i] - __bfloat162float(hb);
        h[i] = __bfloat16_as_ushort(hb);
        l[i] = __bfloat16_as_ushort(__float2bfloat16(r));
    }
    *(uint2*)(hiB + eoff) = make_uint2((uint32_t)h[0] | ((uint32_t)h[1] << 16),
                                       (uint32_t)h[2] | ((uint32_t)h[3] << 16));
    *(uint2*)(loB + eoff) = make_uint2((uint32_t)l[0] | ((uint32_t)l[1] << 16),
                                       (uint32_t)l[2] | ((uint32_t)l[3] << 16));
}
__device__ __forceinline__ void split2pack(float a, float b, uint32_t& hi, uint32_t& lo) {
    __nv_bfloat16 ah = __float2bfloat16(a), bh = __float2bfloat16(b);
    float ar = a - __bfloat162float(ah);
    float br = b - __bfloat162float(bh);
    hi = (uint32_t)__bfloat16_as_ushort(ah) | ((uint32_t)__bfloat16_as_ushort(bh) << 16);
    lo = (uint32_t)__bfloat16_as_ushort(__float2bfloat16(ar)) |
         ((uint32_t)__bfloat16_as_ushort(__float2bfloat16(br)) << 16);
}
__device__ __forceinline__ int clamp8(int v) {
    return v > 127 ? 127 : (v < -127 ? -127 : v);
}
// quantize 2 floats -> packed s8 hi pair + lo pair (2 bytes each)
__device__ __forceinline__ void q8pack2(float a, float b, uint32_t& hp, uint32_t& lp) {
    int ah = clamp8(__float2int_rn(a * QSCL));
    int bh = clamp8(__float2int_rn(b * QSCL));
    float ar = fmaf((float)-ah, QINV, a);
    float br = fmaf((float)-bh, QINV, b);
    int al = clamp8(__float2int_rn(ar * QRES));
    int bl = clamp8(__float2int_rn(br * QRES));
    hp = (uint32_t)(ah & 0xFF) | ((uint32_t)(bh & 0xFF) << 8);
    lp = (uint32_t)(al & 0xFF) | ((uint32_t)(bl & 0xFF) << 8);
}
__device__ __forceinline__ float fexp(float x) {
    float y = x * 1.4426950408889634f;
    y = fmaxf(y, -126.0f);
    float t = y + 12582912.0f;
    float f = y - (t - 12582912.0f);
    float p =            1.3333558146e-3f;
    p = fmaf(p, f, 9.6181291076e-3f);
    p = fmaf(p, f, 5.5504108664e-2f);
    p = fmaf(p, f, 2.4022650696e-1f);
    p = fmaf(p, f, 6.9314718056e-1f);
    p = fmaf(p, f, 1.0f);
    int e = (__float_as_int(t) - 0x4b400000 + 127) << 23;
    return p * __int_as_float(e);
}

// ============================================================================
// Kernel 0: split all 4 weight matrices into bf16 hi/lo.
// ============================================================================
__global__ __launch_bounds__(256) void wsplit_kernel(
    const float* __restrict__ Wq, const float* __restrict__ Wk,
    const float* __restrict__ Wv, const float* __restrict__ Wlast)
{
    int g = blockIdx.x * 256 + threadIdx.x;
    int m = g / 18432, idx = g % 18432;
    const float* src = (m == 0) ? Wq : (m == 1) ? Wk : (m == 2) ? Wv : Wlast;
    __nv_bfloat16 *dh, *dl;
    if (m == 0)      { dh = g_Wqh; dl = g_Wql; }
    else if (m == 1) { dh = g_Wkh; dl = g_Wkl; }
    else if (m == 2) { dh = g_Wvh; dl = g_Wvl; }
    else             { dh = g_Wh;  dl = g_Wl;  }
    float4 v = *(const float4*)(src + idx * 4);
    split4(dh, dl, idx * 4, v);
}

// ============================================================================
// Kernel 1: fused QKV projection. Q,K epilogue -> s8 hi/lo; V -> bf16 hi/lo.
// ============================================================================
#define XP 136
#define WROW 144
#define WTILE (96 * WROW)
#define PJ_WBASE (2 * 64 * XP * 2)
#define PJ_SMEM (PJ_WBASE + 6 * WTILE)

__global__ __launch_bounds__(256, 1) void projmma_kernel(const float* __restrict__ x) {
    extern __shared__ char smraw[];
    __nv_bfloat16* Xh = (__nv_bfloat16*)smraw;
    __nv_bfloat16* Xl = Xh + 64 * XP;
    const uint32_t base = s2u(smraw);
    const uint32_t XhS = base, XlS = base + 17408, WB = base + PJ_WBASE;

    const int l0 = blockIdx.x * 128;
    const int b  = blockIdx.z;
    const int tid = threadIdx.x, wid = tid >> 5, lane = tid & 31;
    const int wm = wid & 1, wn = wid >> 1;

    const int gr = lane >> 2, c2 = (lane & 3) * 2;
    const uint32_t kla = (lane & 7) + ((lane >> 4) << 3);
    const uint32_t mla = ((lane >> 3) & 1) * 8 + wm * 64;
    const uint32_t bofs = ((wn * 24 + (lane & 7)) * 72 + (((lane >> 3) & 1) << 3)) * 2;

    const __nv_bfloat16* Wsrc[6] = {g_Wqh, g_Wql, g_Wkh, g_Wkl, g_Wvh, g_Wvl};

    float D[3][4][3][4];
#pragma unroll
    for (int w = 0; w < 3; ++w)
#pragma unroll
        for (int mf = 0; mf < 4; ++mf)
#pragma unroll
            for (int nf = 0; nf < 3; ++nf)
#pragma unroll
                for (int e = 0; e < 4; ++e) D[w][mf][nf][e] = 0.f;

    const float* xb = x + (size_t)b * CIN * LSEQ + l0;

    for (int c0 = 0; c0 < CIN; c0 += 64) {
        __syncthreads();
#pragma unroll
        for (int it = 0; it < 18; ++it) {
            int idx = tid + it * 256;
            int t = idx / 768, r = idx % 768;
            int o = r >> 3, c16 = r & 7;
            cpa16(WB + t * WTILE + o * WROW + c16 * 16,
                  Wsrc[t] + (size_t)o * CIN + c0 + c16 * 8);
        }
        CP_COMMIT();
#pragma unroll
        for (int it = 0; it < 8; ++it) {
            int idx = tid + it * 256;
            int c = idx >> 5, l4 = idx & 31;
            float4 v = *(const float4*)(xb + (size_t)(c0 + c) * LSEQ + l4 * 4);
            split4(Xh, Xl, c * XP + l4 * 4, v);
        }
        CP_WAIT0();
        __syncthreads();

#pragma unroll
        for (int ks = 0; ks < 4; ++ks) {
            uint32_t A[4][4], L[4][4];
            const uint32_t arow = (ks * 16 + kla) * XP;
#pragma unroll
            for (int mf = 0; mf < 4; ++mf) {
                ldsm4t(A[mf], XhS + (arow + mla + mf * 16) * 2);
                ldsm4t(L[mf], XlS + (arow + mla + mf * 16) * 2);
            }
#pragma unroll
            for (int w = 0; w < 3; ++w) {
                const uint32_t whS = WB + (w * 2) * WTILE;
                const uint32_t wlS = whS + WTILE;
                uint32_t Bf[3][2];
#pragma unroll
                for (int nf = 0; nf < 3; ++nf)
                    ldsm2(Bf[nf], whS + bofs + nf * 8 * WROW + ks * 32);
#pragma unroll
                for (int mf = 0; mf < 4; ++mf)
#pragma unroll
                    for (int nf = 0; nf < 3; ++nf) mma_bf16(D[w][mf][nf], A[mf], Bf[nf]);
#pragma unroll
                for (int mf = 0; mf < 4; ++mf)
#pragma unroll
                    for (int nf = 0; nf < 3; ++nf) mma_bf16(D[w][mf][nf], L[mf], Bf[nf]);
#pragma unroll
                for (int nf = 0; nf < 3; ++nf)
                    ldsm2(Bf[nf], wlS + bofs + nf * 8 * WROW + ks * 32);
#pragma unroll
                for (int mf = 0; mf < 4; ++mf)
#pragma unroll
                    for (int nf = 0; nf < 3; ++nf) mma_bf16(D[w][mf][nf], A[mf], Bf[nf]);
            }
        }
    }

    // --- epilogue: Q (w=0), K (w=1) -> s8 hi/lo; V (w=2) -> bf16 hi/lo
    signed char* S8H[2] = {g_Q8h, g_K8h};
    signed char* S8L[2] = {g_Q8l, g_K8l};
#pragma unroll
    for (int w = 0; w < 2; ++w) {
#pragma unroll
        for (int mf = 0; mf < 4; ++mf) {
            int row = wm * 64 + mf * 16 + gr;
            size_t rb = ((size_t)b * LSEQ + l0 + row) * CH;
#pragma unroll
            for (int nf = 0; nf < 3; ++nf) {
                int col = wn * 24 + nf * 8 + c2;
                uint32_t hp, lp;
                q8pack2(D[w][mf][nf][0], D[w][mf][nf][1], hp, lp);
                *(uint16_t*)(S8H[w] + rb + col) = (uint16_t)hp;
                *(uint16_t*)(S8L[w] + rb + col) = (uint16_t)lp;
                q8pack2(D[w][mf][nf][2], D[w][mf][nf][3], hp, lp);
                *(uint16_t*)(S8H[w] + rb + 8 * CH + col) = (uint16_t)hp;
                *(uint16_t*)(S8L[w] + rb + 8 * CH + col) = (uint16_t)lp;
            }
        }
    }
#pragma unroll
    for (int mf = 0; mf < 4; ++mf) {
        int row = wm * 64 + mf * 16 + gr;
        size_t rb = ((size_t)b * LSEQ + l0 + row) * CH;
#pragma unroll
        for (int nf = 0; nf < 3; ++nf) {
            int col = wn * 24 + nf * 8 + c2;
            uint32_t h, l;
            split2pack(D[2][mf][nf][0], D[2][mf][nf][1], h, l);
            *(uint32_t*)(g_Vh + rb + col) = h;
            *(uint32_t*)(g_Vl + rb + col) = l;
            split2pack(D[2][mf][nf][2], D[2][mf][nf][3], h, l);
            *(uint32_t*)(g_Vh + rb + 8 * CH + col) = h;
            *(uint32_t*)(g_Vl + rb + 8 * CH + col) = l;
        }
    }
}

// ============================================================================
// Kernel 2: fused flash attention. QK^T via s8 IMMA m16n8k32 (split-2,
// exact s32 accumulation, shared power-of-2 scales); softmax + PV in
// fp32/bf16 exactly as before. 256 threads / 8 warps, M=32 warp tiles,
// 256-query tile, 64-key chunks, double-buffered cp.async.
// smem: Q8h 28672 | Q8l 28672 | 2 x {K8h 7168, K8l 7168, Vh 13312, Vl 13312}
// ============================================================================
#define FAP8 112
#define QT8 (256 * FAP8)              // 28672 per half
#define KT8 (64 * FAP8)               // 7168 per half
#define VTPB (64 * 208)               // 13312 per half
#define KVBUFB (2 * KT8 + 2 * VTPB)   // 40960
#define FA_SMEM (2 * QT8 + 2 * KVBUFB)  // 139264

__global__ __launch_bounds__(256, 1) void fattn_kernel() {
    extern __shared__ char smraw[];
    const uint32_t base = s2u(smraw);
    const uint32_t QhS = base, QlS = base + QT8, KVB = base + 2 * QT8;
    const int tid = threadIdx.x, wid = tid >> 5, lane = tid & 31;
    const int b = blockIdx.y, q0 = blockIdx.x * 256;
    const int gr = lane >> 2, c2 = (lane & 3) * 2;

    // ---- stage Q s8 hi/lo (resident)
    {
        const signed char* Qh = g_Q8h + ((size_t)b * LSEQ + q0) * CH;
        const signed char* Ql = g_Q8l + ((size_t)b * LSEQ + q0) * CH;
#pragma unroll
        for (int it = 0; it < 12; ++it) {
            int idx = tid + it * 256;            // 0..3071
            int half = idx / 1536, w = idx % 1536;
            int r = w / 6, seg = w % 6;
            cpa16((half ? QlS : QhS) + r * FAP8 + seg * 16,
                  (half ? Ql : Qh) + (size_t)r * CH + seg * 16);
        }
        CP_COMMIT();
    }

    float O[2][12][4];
#pragma unroll
    for (int mf = 0; mf < 2; ++mf)
#pragma unroll
        for (int nf = 0; nf < 12; ++nf)
#pragma unroll
            for (int e = 0; e < 4; ++e) O[mf][nf][e] = 0.f;
    float m[4], ls[4];
#pragma unroll
    for (int i = 0; i < 4; ++i) { m[i] = -1e30f; ls[i] = 0.f; }

    const signed char* K8[2] = {g_K8h + (size_t)b * LSEQ * CH,
                                g_K8l + (size_t)b * LSEQ * CH};
    const __nv_bfloat16* Vb[2] = {g_Vh + (size_t)b * LSEQ * CH,
                                  g_Vl + (size_t)b * LSEQ * CH};

    // lane addressing
    const uint32_t aQ8 = (wid * 32 + (lane & 15)) * FAP8 + ((lane >> 4) << 4);
    const uint32_t bK8 = ((lane & 7) + ((lane >> 4) << 3)) * FAP8 + (((lane >> 3) & 1) << 4);
    const uint32_t browV4 = (lane & 15) * 208 + (lane >> 4) * 16;

    auto issue = [&](int ct, uint32_t bufbase) {
        const int k0 = (ct & 63) * 64;
#pragma unroll
        for (int it = 0; it < 9; ++it) {
            int idx = tid + it * 256;            // 0..2303
            if (idx < 768) {
                int half = idx / 384, w = idx % 384;
                int r = w / 6, seg = w % 6;
                cpa16(bufbase + half * KT8 + r * FAP8 + seg * 16,
                      K8[half] + (size_t)(k0 + r) * CH + seg * 16);
            } else {
                int v = idx - 768;
                int half = v / 768, w = v % 768;
                int r = w / 12, seg = w % 12;
                cpa16(bufbase + 2 * KT8 + half * VTPB + r * 208 + seg * 16,
                      (const char*)Vb[half] + (size_t)(k0 + r) * (CH * 2) + seg * 16);
            }
        }
        CP_COMMIT();
    };

    issue(0, KVB);
    issue(1, KVB + KVBUFB);
    CP_WAIT1();            // Q + chunk0 resident
    __syncthreads();

    for (int ct = 0; ct < 64; ++ct) {
        const uint32_t buf = KVB + (ct & 1) * KVBUFB;
        const uint32_t KhS = buf, KlS = buf + KT8;
        const uint32_t VhS = buf + 2 * KT8, VlS = buf + 2 * KT8 + VTPB;

        // ---- S = Q K^T via s8 IMMA, two nf-halves of 4 (keys nh*32..+31)
        float S[2][8][4];
#pragma unroll
        for (int nh = 0; nh < 2; ++nh) {
            int acc[2][4][4];
#pragma unroll
            for (int mf = 0; mf < 2; ++mf)
#pragma unroll
                for (int nf = 0; nf < 4; ++nf)
#pragma unroll
                    for (int e = 0; e < 4; ++e) acc[mf][nf][e] = 0;
            // hh pass
#pragma unroll
            for (int ks = 0; ks < 3; ++ks) {
                uint32_t QA0[4], QA1[4], KB[4][2];
                ldsm4(QA0, QhS + aQ8 + ks * 32);
                ldsm4(QA1, QhS + aQ8 + 16 * FAP8 + ks * 32);
#pragma unroll
                for (int p = 0; p < 2; ++p) {
                    uint32_t r4[4];
                    ldsm4(r4, KhS + bK8 + (nh * 32 + p * 16) * FAP8 + ks * 32);
                    KB[2 * p][0] = r4[0]; KB[2 * p][1] = r4[1];
                    KB[2 * p + 1][0] = r4[2]; KB[2 * p + 1][1] = r4[3];
                }
#pragma unroll
                for (int nf = 0; nf < 4; ++nf) {
                    mma_s8(acc[0][nf], QA0, KB[nf]);
                    mma_s8(acc[1][nf], QA1, KB[nf]);
                }
            }
#pragma unroll
            for (int mf = 0; mf < 2; ++mf)
#pragma unroll
                for (int nf = 0; nf < 4; ++nf)
#pragma unroll
                    for (int e = 0; e < 4; ++e)
                        S[mf][nh * 4 + nf][e] = (float)acc[mf][nf][e] * SQ2;
            // cross pass (Qh*Kl + Ql*Kh, shared scale s^2/128)
#pragma unroll
            for (int mf = 0; mf < 2; ++mf)
#pragma unroll
                for (int nf = 0; nf < 4; ++nf)
#pragma unroll
                    for (int e = 0; e < 4; ++e) acc[mf][nf][e] = 0;
#pragma unroll
            for (int ks = 0; ks < 3; ++ks) {
                uint32_t QA0[4], QA1[4], QB0[4], QB1[4], KB[4][2];
                ldsm4(QA0, QhS + aQ8 + ks * 32);
                ldsm4(QA1, QhS + aQ8 + 16 * FAP8 + ks * 32);
                ldsm4(QB0, QlS + aQ8 + ks * 32);
                ldsm4(QB1, QlS + aQ8 + 16 * FAP8 + ks * 32);
#pragma unroll
                for (int p = 0; p < 2; ++p) {
                    uint32_t r4[4];
                    ldsm4(r4, KlS + bK8 + (nh * 32 + p * 16) * FAP8 + ks * 32);
                    KB[2 * p][0] = r4[0]; KB[2 * p][1] = r4[1];
                    KB[2 * p + 1][0] = r4[2]; KB[2 * p + 1][1] = r4[3];
                }
#pragma unroll
                for (int nf = 0; nf < 4; ++nf) {
                    mma_s8(acc[0][nf], QA0, KB[nf]);
                    mma_s8(acc[1][nf], QA1, KB[nf]);
                }
#pragma unroll
                for (int p = 0; p < 2; ++p) {
                    uint32_t r4[4];
                    ldsm4(r4, KhS + bK8 + (nh * 32 + p * 16) * FAP8 + ks * 32);
                    KB[2 * p][0] = r4[0]; KB[2 * p][1] = r4[1];
                    KB[2 * p + 1][0] = r4[2]; KB[2 * p + 1][1] = r4[3];
                }
#pragma unroll
                for (int nf = 0; nf < 4; ++nf) {
                    mma_s8(acc[0][nf], QB0, KB[nf]);
                    mma_s8(acc[1][nf], QB1, KB[nf]);
                }
            }
#pragma unroll
            for (int mf = 0; mf < 2; ++mf)
#pragma unroll
                for (int nf = 0; nf < 4; ++nf)
#pragma unroll
                    for (int e = 0; e < 4; ++e)
                        S[mf][nh * 4 + nf][e] += (float)acc[mf][nf][e] * SQ2R;
        }

        // ---- online softmax per M-frag (unchanged)
#pragma unroll
        for (int mf = 0; mf < 2; ++mf) {
            float r0 = -1e30f, r1 = -1e30f;
#pragma unroll
            for (int nf = 0; nf < 8; ++nf) {
                r0 = fmaxf(r0, fmaxf(S[mf][nf][0], S[mf][nf][1]));
                r1 = fmaxf(r1, fmaxf(S[mf][nf][2], S[mf][nf][3]));
            }
            r0 = fmaxf(r0, __shfl_xor_sync(0xffffffffu, r0, 1));
            r0 = fmaxf(r0, __shfl_xor_sync(0xffffffffu, r0, 2));
            r1 = fmaxf(r1, __shfl_xor_sync(0xffffffffu, r1, 1));
            r1 = fmaxf(r1, __shfl_xor_sync(0xffffffffu, r1, 2));
            const float nm0 = fmaxf(m[2 * mf], r0), nm1 = fmaxf(m[2 * mf + 1], r1);
            const float sc0 = fexp(m[2 * mf] - nm0), sc1 = fexp(m[2 * mf + 1] - nm1);
            m[2 * mf] = nm0; m[2 * mf + 1] = nm1;

            float ps0 = 0.f, ps1 = 0.f;
#pragma unroll
            for (int nf = 0; nf < 8; ++nf) {
                S[mf][nf][0] = fexp(S[mf][nf][0] - nm0);
                S[mf][nf][1] = fexp(S[mf][nf][1] - nm0);
                S[mf][nf][2] = fexp(S[mf][nf][2] - nm1);
                S[mf][nf][3] = fexp(S[mf][nf][3] - nm1);
                ps0 += S[mf][nf][0] + S[mf][nf][1];
                ps1 += S[mf][nf][2] + S[mf][nf][3];
            }
            ps0 += __shfl_xor_sync(0xffffffffu, ps0, 1);
            ps0 += __shfl_xor_sync(0xffffffffu, ps0, 2);
            ps1 += __shfl_xor_sync(0xffffffffu, ps1, 1);
            ps1 += __shfl_xor_sync(0xffffffffu, ps1, 2);
            ls[2 * mf]     = ls[2 * mf] * sc0 + ps0;
            ls[2 * mf + 1] = ls[2 * mf + 1] * sc1 + ps1;
#pragma unroll
            for (int nf = 0; nf < 12; ++nf) {
                O[mf][nf][0] *= sc0; O[mf][nf][1] *= sc0;
                O[mf][nf][2] *= sc1; O[mf][nf][3] *= sc1;
            }
        }

        // ---- O += P V (split-3 bf16, unchanged)
#pragma unroll
        for (int ks = 0; ks < 4; ++ks) {
            uint32_t PH0[4], PL0[4], PH1[4], PL1[4];
            split2pack(S[0][2 * ks][0],     S[0][2 * ks][1],     PH0[0], PL0[0]);
            split2pack(S[0][2 * ks][2],     S[0][2 * ks][3],     PH0[1], PL0[1]);
            split2pack(S[0][2 * ks + 1][0], S[0][2 * ks + 1][1], PH0[2], PL0[2]);
            split2pack(S[0][2 * ks + 1][2], S[0][2 * ks + 1][3], PH0[3], PL0[3]);
            split2pack(S[1][2 * ks][0],     S[1][2 * ks][1],     PH1[0], PL1[0]);
            split2pack(S[1][2 * ks][2],     S[1][2 * ks][3],     PH1[1], PL1[1]);
            split2pack(S[1][2 * ks + 1][0], S[1][2 * ks + 1][1], PH1[2], PL1[2]);
            split2pack(S[1][2 * ks + 1][2], S[1][2 * ks + 1][3], PH1[3], PL1[3]);

            uint32_t Vf[12][2];
            const uint32_t vkr = ks * 16 * 208 + browV4;
#pragma unroll
            for (int p = 0; p < 6; ++p) {
                uint32_t r4[4];
                ldsm4t(r4, VhS + vkr + p * 32);
                Vf[2 * p][0] = r4[0]; Vf[2 * p][1] = r4[1];
                Vf[2 * p + 1][0] = r4[2]; Vf[2 * p + 1][1] = r4[3];
            }
#pragma unroll
            for (int nf = 0; nf < 12; ++nf) {
                mma_bf16(O[0][nf], PH0, Vf[nf]);
                mma_bf16(O[1][nf], PH1, Vf[nf]);
            }
#pragma unroll
            for (int nf = 0; nf < 12; ++nf) {
                mma_bf16(O[0][nf], PL0, Vf[nf]);
                mma_bf16(O[1][nf], PL1, Vf[nf]);
            }
#pragma unroll
            for (int p = 0; p < 6; ++p) {
                uint32_t r4[4];
                ldsm4t(r4, VlS + vkr + p * 32);
                Vf[2 * p][0] = r4[0]; Vf[2 * p][1] = r4[1];
                Vf[2 * p + 1][0] = r4[2]; Vf[2 * p + 1][1] = r4[3];
            }
#pragma unroll
            for (int nf = 0; nf < 12; ++nf) {
                mma_bf16(O[0][nf], PH0, Vf[nf]);
                mma_bf16(O[1][nf], PH1, Vf[nf]);
            }
        }

        __syncthreads();
        issue(ct + 2, buf);
        CP_WAIT1();
        __syncthreads();
    }

    // ---- epilogue: normalize, split, write g_Oh/g_Ol
#pragma unroll
    for (int mf = 0; mf < 2; ++mf) {
        const float i0 = 1.f / ls[2 * mf], i1 = 1.f / ls[2 * mf + 1];
        size_t rb = ((size_t)b * LSEQ + q0 + wid * 32 + mf * 16 + gr) * CH;
#pragma unroll
        for (int nf = 0; nf < 12; ++nf) {
            int col = nf * 8 + c2;
            uint32_t h, l;
            split2pack(O[mf][nf][0] * i0, O[mf][nf][1] * i0, h, l);
            *(uint32_t*)(g_Oh + rb + col) = h;
            *(uint32_t*)(g_Ol + rb + col) = l;
            split2pack(O[mf][nf][2] * i1, O[mf][nf][3] * i1, h, l);
            *(uint32_t*)(g_Oh + rb + 8 * CH + col) = h;
            *(uint32_t*)(g_Ol + rb + 8 * CH + col) = l;
        }
    }
}

// ============================================================================
// Kernel 3: y[b,o,l] = gamma * (Wlast . O) + x via split-bf16 MMA (unchanged).
// ============================================================================
#define FAP 104
#define OM_SMEM (2 * 128 * FAP * 2 + 2 * 96 * FAP * 2)

__global__ __launch_bounds__(256, 2) void outmma_kernel(
    const float* __restrict__ x,
    const float* __restrict__ gammap,
    float* __restrict__ out)
{
    extern __shared__ char smraw[];
    const uint32_t base = s2u(smraw);
    const uint32_t OhS = base, OlS = base + 26624, WhS = base + 53248, WlS = base + 73216;
    float* sst = (float*)smraw;

    const int l0 = blockIdx.x * 128;
    const int o0 = blockIdx.y * 96;
    const int b  = blockIdx.z;
    const int tid = threadIdx.x, wid = tid >> 5, lane = tid & 31;
    const int wm = wid & 1, wn = wid >> 1;
    const int gr = lane >> 2, c2 = (lane & 3) * 2;
    const float gamma = gammap[0];

    {
        const __nv_bfloat16* Oh = g_Oh + ((size_t)b * LSEQ + l0) * CH;
        const __nv_bfloat16* Ol = g_Ol + ((size_t)b * LSEQ + l0) * CH;
#pragma unroll
        for (int it = 0; it < 6; ++it) {
            int idx = tid + it * 256;
            int r = idx / 12, c16 = idx % 12;
            cpa16(OhS + r * 208 + c16 * 16, Oh + (size_t)r * CH + c16 * 8);
            cpa16(OlS + r * 208 + c16 * 16, Ol + (size_t)r * CH + c16 * 8);
        }
        const __nv_bfloat16* Wh = g_Wh + (size_t)o0 * CH;
        const __nv_bfloat16* Wl = g_Wl + (size_t)o0 * CH;
#pragma unroll
        for (int it = 0; it < 5; ++it) {
            int idx = tid + it * 256;
            if (idx < 1152) {
                int r = idx / 12, c16 = idx % 12;
                cpa16(WhS + r * 208 + c16 * 16, Wh + (size_t)r * CH + c16 * 8);
                cpa16(WlS + r * 208 + c16 * 16, Wl + (size_t)r * CH + c16 * 8);
            }
        }
        CP_COMMIT();
        CP_WAIT0();
    }
    __syncthreads();

    const uint32_t aoff = ((wm * 64 + (lane & 15)) * FAP + ((lane >> 4) << 3)) * 2;
    const uint32_t bofs = ((wn * 24 + (lane & 7)) * FAP + (((lane >> 3) & 1) << 3)) * 2;

    float D[4][3][4];
#pragma unroll
    for (int mf = 0; mf < 4; ++mf)
#pragma unroll
        for (int nf = 0; nf < 3; ++nf)
#pragma unroll
            for (int e = 0; e < 4; ++e) D[mf][nf][e] = 0.f;

#pragma unroll
    for (int ks = 0; ks < 6; ++ks) {
        uint32_t A[4][4], L[4][4], Bf[3][2];
#pragma unroll
        for (int mf = 0; mf < 4; ++mf)
            ldsm4(A[mf], OhS + aoff + mf * 16 * (FAP * 2) + ks * 32);
#pragma unroll
        for (int nf = 0; nf < 3; ++nf)
            ldsm2(Bf[nf], WhS + bofs + nf * 8 * (FAP * 2) + ks * 32);
#pragma unroll
        for (int mf = 0; mf < 4; ++mf)
#pragma unroll
            for (int nf = 0; nf < 3; ++nf) mma_bf16(D[mf][nf], A[mf], Bf[nf]);
#pragma unroll
        for (int mf = 0; mf < 4; ++mf)
            ldsm4(L[mf], OlS + aoff + mf * 16 * (FAP * 2) + ks * 32);
#pragma unroll
        for (int mf = 0; mf < 4; ++mf)
#pragma unroll
            for (int nf = 0; nf < 3; ++nf) mma_bf16(D[mf][nf], L[mf], Bf[nf]);
#pragma unroll
        for (int nf = 0; nf < 3; ++nf)
            ldsm2(Bf[nf], WlS + bofs + nf * 8 * (FAP * 2) + ks * 32);
#pragma unroll
        for (int mf = 0; mf < 4; ++mf)
#pragma unroll
            for (int nf = 0; nf < 3; ++nf) mma_bf16(D[mf][nf], A[mf], Bf[nf]);
    }
    __syncthreads();

#pragma unroll
    for (int mf = 0; mf < 4; ++mf) {
        int row = wm * 64 + mf * 16 + gr;
#pragma unroll
        for (int nf = 0; nf < 3; ++nf) {
            int col = wn * 24 + nf * 8 + c2;
            sst[(col)     * 132 + row]     = D[mf][nf][0];
            sst[(col + 1) * 132 + row]     = D[mf][nf][1];
            sst[(col)     * 132 + row + 8] = D[mf][nf][2];
            sst[(col + 1) * 132 + row + 8] = D[mf][nf][3];
        }
    }
    __syncthreads();

#pragma unroll
    for (int it = 0; it < 12; ++it) {
        int idx = tid + it * 256;
        int o = idx >> 5, l4 = idx & 31;
        float4 v = *(const float4*)&sst[o * 132 + l4 * 4];
        size_t gbase = (size_t)b * COUTC * LSEQ + (size_t)(o0 + o) * LSEQ + l0 + l4 * 4;
        float4 xr = *(const float4*)(x + gbase);
        *(float4*)(out + gbase) = make_float4(fmaf(gamma, v.x, xr.x),
                                              fmaf(gamma, v.y, xr.y),
                                              fmaf(gamma, v.z, xr.z),
                                              fmaf(gamma, v.w, xr.w));
    }
}

// ============================================================================
extern "C" void kernel_launch(void* const* d_in, const int* in_sizes, int n_in,
                              void* d_out, int out_size) {
    const float* x     = (const float*)d_in[0];
    const float* Wq    = (const float*)d_in[1];
    const float* Wk    = (const float*)d_in[2];
    const float* Wv    = (const float*)d_in[3];
    const float* Wl    = (const float*)d_in[4];
    const float* gamma = (const float*)d_in[5];
    float* out = (float*)d_out;

    cudaFuncSetAttribute(projmma_kernel, cudaFuncAttributeMaxDynamicSharedMemorySize, PJ_SMEM);
    cudaFuncSetAttribute(fattn_kernel,   cudaFuncAttributeMaxDynamicSharedMemorySize, FA_SMEM);
    cudaFuncSetAttribute(outmma_kernel,  cudaFuncAttributeMaxDynamicSharedMemorySize, OM_SMEM);

    wsplit_kernel<<<288, 256>>>(Wq, Wk, Wv, Wl);
    projmma_kernel<<<dim3(32, 1, 8), 256, PJ_SMEM>>>(x);
    fattn_kernel<<<dim3(16, 8), 256, FA_SMEM>>>();
    outmma_kernel<<<dim3(32, 8, 8), 256, OM_SMEM>>>(x, gamma, out);
}

// round 17
// speedup vs baseline: 1.7117x; 1.7117x over previous
#include <cuda_runtime.h>
#include <cuda_bf16.h>
#include <cstdint>
#include <cstddef>

#define BB    8
#define CIN   768
#define LSEQ  4096
#define CH    96
#define COUTC 768

// ---- device-global scratch: pre-split bf16 hi/lo pairs ----
__device__ __nv_bfloat16 g_Qh[BB * LSEQ * CH], g_Ql[BB * LSEQ * CH];
__device__ __nv_bfloat16 g_Kh[BB * LSEQ * CH], g_Kl[BB * LSEQ * CH];
__device__ __nv_bfloat16 g_Vh[BB * LSEQ * CH], g_Vl[BB * LSEQ * CH];
__device__ __nv_bfloat16 g_Oh[BB * LSEQ * CH], g_Ol[BB * LSEQ * CH];
__device__ __nv_bfloat16 g_Wh[COUTC * CH],     g_Wl[COUTC * CH];
__device__ __nv_bfloat16 g_Wqh[CH * CIN], g_Wql[CH * CIN];
__device__ __nv_bfloat16 g_Wkh[CH * CIN], g_Wkl[CH * CIN];
__device__ __nv_bfloat16 g_Wvh[CH * CIN], g_Wvl[CH * CIN];

// ============================================================================
// PTX helpers
// ============================================================================
__device__ __forceinline__ uint32_t s2u(const void* p) {
    return (uint32_t)__cvta_generic_to_shared(p);
}
__device__ __forceinline__ void ldsm4(uint32_t r[4], uint32_t a) {
    asm volatile("ldmatrix.sync.aligned.m8n8.x4.shared.b16 {%0,%1,%2,%3}, [%4];"
                 : "=r"(r[0]), "=r"(r[1]), "=r"(r[2]), "=r"(r[3]) : "r"(a));
}
__device__ __forceinline__ void ldsm4t(uint32_t r[4], uint32_t a) {
    asm volatile("ldmatrix.sync.aligned.m8n8.x4.trans.shared.b16 {%0,%1,%2,%3}, [%4];"
                 : "=r"(r[0]), "=r"(r[1]), "=r"(r[2]), "=r"(r[3]) : "r"(a));
}
__device__ __forceinline__ void ldsm2(uint32_t r[2], uint32_t a) {
    asm volatile("ldmatrix.sync.aligned.m8n8.x2.shared.b16 {%0,%1}, [%2];"
                 : "=r"(r[0]), "=r"(r[1]) : "r"(a));
}
__device__ __forceinline__ void mma_bf16(float d[4], const uint32_t a[4], const uint32_t b[2]) {
    asm volatile("mma.sync.aligned.m16n8k16.row.col.f32.bf16.bf16.f32 "
                 "{%0,%1,%2,%3}, {%4,%5,%6,%7}, {%8,%9}, {%0,%1,%2,%3};"
                 : "+f"(d[0]), "+f"(d[1]), "+f"(d[2]), "+f"(d[3])
                 : "r"(a[0]), "r"(a[1]), "r"(a[2]), "r"(a[3]), "r"(b[0]), "r"(b[1]));
}
__device__ __forceinline__ void cpa16(uint32_t dst, const void* src) {
    asm volatile("cp.async.cg.shared.global [%0], [%1], 16;" :: "r"(dst), "l"(src));
}
#define CP_COMMIT() asm volatile("cp.async.commit_group;" ::: "memory")
#define CP_WAIT0()  asm volatile("cp.async.wait_group 0;" ::: "memory")
#define CP_WAIT1()  asm volatile("cp.async.wait_group 1;" ::: "memory")

__device__ __forceinline__ void split4(__nv_bfloat16* hiB, __nv_bfloat16* loB,
                                       int eoff, float4 v) {
    float f[4] = {v.x, v.y, v.z, v.w};
    unsigned short h[4], l[4];
#pragma unroll
    for (int i = 0; i < 4; ++i) {
        __nv_bfloat16 hb = __float2bfloat16(f[i]);
        float r = f[i] - __bfloat162float(hb);
        h[i] = __bfloat16_as_ushort(hb);
        l[i] = __bfloat16_as_ushort(__float2bfloat16(r));
    }
    *(uint2*)(hiB + eoff) = make_uint2((uint32_t)h[0] | ((uint32_t)h[1] << 16),
                                       (uint32_t)h[2] | ((uint32_t)h[3] << 16));
    *(uint2*)(loB + eoff) = make_uint2((uint32_t)l[0] | ((uint32_t)l[1] << 16),
                                       (uint32_t)l[2] | ((uint32_t)l[3] << 16));
}
__device__ __forceinline__ void split2pack(float a, float b, uint32_t& hi, uint32_t& lo) {
    __nv_bfloat16 ah = __float2bfloat16(a), bh = __float2bfloat16(b);
    float ar = a - __bfloat162float(ah);
    float br = b - __bfloat162float(bh);
    hi = (uint32_t)__bfloat16_as_ushort(ah) | ((uint32_t)__bfloat16_as_ushort(bh) << 16);
    lo = (uint32_t)__bfloat16_as_ushort(__float2bfloat16(ar)) |
         ((uint32_t)__bfloat16_as_ushort(__float2bfloat16(br)) << 16);
}
__device__ __forceinline__ float fexp(float x) {
    float y = x * 1.4426950408889634f;
    y = fmaxf(y, -126.0f);
    float t = y + 12582912.0f;
    float f = y - (t - 12582912.0f);
    float p =            1.3333558146e-3f;
    p = fmaf(p, f, 9.6181291076e-3f);
    p = fmaf(p, f, 5.5504108664e-2f);
    p = fmaf(p, f, 2.4022650696e-1f);
    p = fmaf(p, f, 6.9314718056e-1f);
    p = fmaf(p, f, 1.0f);
    int e = (__float_as_int(t) - 0x4b400000 + 127) << 23;
    return p * __int_as_float(e);
}

// ============================================================================
// Kernel 0: split all 4 weight matrices into bf16 hi/lo.
// ============================================================================
__global__ __launch_bounds__(256) void wsplit_kernel(
    const float* __restrict__ Wq, const float* __restrict__ Wk,
    const float* __restrict__ Wv, const float* __restrict__ Wlast)
{
    int g = blockIdx.x * 256 + threadIdx.x;
    int m = g / 18432, idx = g % 18432;
    const float* src = (m == 0) ? Wq : (m == 1) ? Wk : (m == 2) ? Wv : Wlast;
    __nv_bfloat16 *dh, *dl;
    if (m == 0)      { dh = g_Wqh; dl = g_Wql; }
    else if (m == 1) { dh = g_Wkh; dl = g_Wkl; }
    else if (m == 2) { dh = g_Wvh; dl = g_Wvl; }
    else             { dh = g_Wh;  dl = g_Wl;  }
    float4 v = *(const float4*)(src + idx * 4);
    split4(dh, dl, idx * 4, v);
}

// ============================================================================
// Kernel 1: fused QKV projection (R7/R12 version).
// ============================================================================
#define XP 136
#define WROW 144
#define WTILE (96 * WROW)
#define PJ_WBASE (2 * 64 * XP * 2)
#define PJ_SMEM (PJ_WBASE + 6 * WTILE)

__global__ __launch_bounds__(256, 1) void projmma_kernel(const float* __restrict__ x) {
    extern __shared__ char smraw[];
    __nv_bfloat16* Xh = (__nv_bfloat16*)smraw;
    __nv_bfloat16* Xl = Xh + 64 * XP;
    const uint32_t base = s2u(smraw);
    const uint32_t XhS = base, XlS = base + 17408, WB = base + PJ_WBASE;

    const int l0 = blockIdx.x * 128;
    const int b  = blockIdx.z;
    const int tid = threadIdx.x, wid = tid >> 5, lane = tid & 31;
    const int wm = wid & 1, wn = wid >> 1;

    const int gr = lane >> 2, c2 = (lane & 3) * 2;
    const uint32_t kla = (lane & 7) + ((lane >> 4) << 3);
    const uint32_t mla = ((lane >> 3) & 1) * 8 + wm * 64;
    const uint32_t bofs = ((wn * 24 + (lane & 7)) * 72 + (((lane >> 3) & 1) << 3)) * 2;

    const __nv_bfloat16* Wsrc[6] = {g_Wqh, g_Wql, g_Wkh, g_Wkl, g_Wvh, g_Wvl};

    float D[3][4][3][4];
#pragma unroll
    for (int w = 0; w < 3; ++w)
#pragma unroll
        for (int mf = 0; mf < 4; ++mf)
#pragma unroll
            for (int nf = 0; nf < 3; ++nf)
#pragma unroll
                for (int e = 0; e < 4; ++e) D[w][mf][nf][e] = 0.f;

    const float* xb = x + (size_t)b * CIN * LSEQ + l0;

    for (int c0 = 0; c0 < CIN; c0 += 64) {
        __syncthreads();
#pragma unroll
        for (int it = 0; it < 18; ++it) {
            int idx = tid + it * 256;
            int t = idx / 768, r = idx % 768;
            int o = r >> 3, c16 = r & 7;
            cpa16(WB + t * WTILE + o * WROW + c16 * 16,
                  Wsrc[t] + (size_t)o * CIN + c0 + c16 * 8);
        }
        CP_COMMIT();
#pragma unroll
        for (int it = 0; it < 8; ++it) {
            int idx = tid + it * 256;
            int c = idx >> 5, l4 = idx & 31;
            float4 v = *(const float4*)(xb + (size_t)(c0 + c) * LSEQ + l4 * 4);
            split4(Xh, Xl, c * XP + l4 * 4, v);
        }
        CP_WAIT0();
        __syncthreads();

#pragma unroll
        for (int ks = 0; ks < 4; ++ks) {
            uint32_t A[4][4], L[4][4];
            const uint32_t arow = (ks * 16 + kla) * XP;
#pragma unroll
            for (int mf = 0; mf < 4; ++mf) {
                ldsm4t(A[mf], XhS + (arow + mla + mf * 16) * 2);
                ldsm4t(L[mf], XlS + (arow + mla + mf * 16) * 2);
            }
#pragma unroll
            for (int w = 0; w < 3; ++w) {
                const uint32_t whS = WB + (w * 2) * WTILE;
                const uint32_t wlS = whS + WTILE;
                uint32_t Bf[3][2];
#pragma unroll
                for (int nf = 0; nf < 3; ++nf)
                    ldsm2(Bf[nf], whS + bofs + nf * 8 * WROW + ks * 32);
#pragma unroll
                for (int mf = 0; mf < 4; ++mf)
#pragma unroll
                    for (int nf = 0; nf < 3; ++nf) mma_bf16(D[w][mf][nf], A[mf], Bf[nf]);
#pragma unroll
                for (int mf = 0; mf < 4; ++mf)
#pragma unroll
                    for (int nf = 0; nf < 3; ++nf) mma_bf16(D[w][mf][nf], L[mf], Bf[nf]);
#pragma unroll
                for (int nf = 0; nf < 3; ++nf)
                    ldsm2(Bf[nf], wlS + bofs + nf * 8 * WROW + ks * 32);
#pragma unroll
                for (int mf = 0; mf < 4; ++mf)
#pragma unroll
                    for (int nf = 0; nf < 3; ++nf) mma_bf16(D[w][mf][nf], A[mf], Bf[nf]);
            }
        }
    }

    __nv_bfloat16* OH[3] = {g_Qh, g_Kh, g_Vh};
    __nv_bfloat16* OL[3] = {g_Ql, g_Kl, g_Vl};
#pragma unroll
    for (int w = 0; w < 3; ++w) {
#pragma unroll
        for (int mf = 0; mf < 4; ++mf) {
            int row = wm * 64 + mf * 16 + gr;
            size_t rb = ((size_t)b * LSEQ + l0 + row) * CH;
#pragma unroll
            for (int nf = 0; nf < 3; ++nf) {
                int col = wn * 24 + nf * 8 + c2;
                uint32_t h, l;
                split2pack(D[w][mf][nf][0], D[w][mf][nf][1], h, l);
                *(uint32_t*)(OH[w] + rb + col) = h;
                *(uint32_t*)(OL[w] + rb + col) = l;
                split2pack(D[w][mf][nf][2], D[w][mf][nf][3], h, l);
                *(uint32_t*)(OH[w] + rb + 8 * CH + col) = h;
                *(uint32_t*)(OL[w] + rb + 8 * CH + col) = l;
            }
        }
    }
}

// ============================================================================
// Kernel 2: fused flash attention, M=32 warp tiles (R12 version) + vote-
// guarded O-rescale skip (near-one-hot softmax: row max rarely updates).
// ============================================================================
#define FAP 104
#define QREG (256 * FAP * 2)
#define KTPB (64 * FAP * 2)
#define KVBUF (4 * KTPB)
#define FA_SMEM (2 * QREG + 2 * KVBUF)

__global__ __launch_bounds__(256, 1) void fattn_kernel() {
    extern __shared__ char smraw[];
    const uint32_t base = s2u(smraw);
    const uint32_t QhS = base, QlS = base + QREG, KVB = base + 2 * QREG;
    const int tid = threadIdx.x, wid = tid >> 5, lane = tid & 31;
    const int b = blockIdx.y, q0 = blockIdx.x * 256;
    const int gr = lane >> 2, c2 = (lane & 3) * 2;

    // ---- stage Q hi/lo (resident for whole kernel)
    {
        const __nv_bfloat16* Qh = g_Qh + ((size_t)b * LSEQ + q0) * CH;
        const __nv_bfloat16* Ql = g_Ql + ((size_t)b * LSEQ + q0) * CH;
#pragma unroll
        for (int it = 0; it < 12; ++it) {
            int idx = tid + it * 256;
            int r = idx / 12, c16 = idx % 12;
            cpa16(QhS + r * 208 + c16 * 16, Qh + (size_t)r * CH + c16 * 8);
            cpa16(QlS + r * 208 + c16 * 16, Ql + (size_t)r * CH + c16 * 8);
        }
        CP_COMMIT();
    }

    float O[2][12][4];
#pragma unroll
    for (int mf = 0; mf < 2; ++mf)
#pragma unroll
        for (int nf = 0; nf < 12; ++nf)
#pragma unroll
            for (int e = 0; e < 4; ++e) O[mf][nf][e] = 0.f;
    float m[4], ls[4];
#pragma unroll
    for (int i = 0; i < 4; ++i) { m[i] = -1e30f; ls[i] = 0.f; }

    const __nv_bfloat16* srcs[4] = {
        g_Kh + (size_t)b * LSEQ * CH, g_Kl + (size_t)b * LSEQ * CH,
        g_Vh + (size_t)b * LSEQ * CH, g_Vl + (size_t)b * LSEQ * CH };

    const uint32_t arowQ = ((wid * 32 + (lane & 15)) * FAP + ((lane >> 4) << 3)) * 2;
    const uint32_t bofsK4 = (lane & 7) * 208 + ((lane >> 3) & 1) * 16 + (lane >> 4) * 8 * 208;
    const uint32_t browV4 = (lane & 15) * 208 + (lane >> 4) * 16;

    auto issue = [&](int ct, uint32_t bufbase) {
        const int k0 = (ct & 63) * 64;
#pragma unroll
        for (int it = 0; it < 12; ++it) {
            int idx = tid + it * 256;
            int tile = idx / 768, w = idx % 768;
            int r = w / 12, c16 = w % 12;
            cpa16(bufbase + tile * KTPB + r * 208 + c16 * 16,
                  srcs[tile] + (size_t)(k0 + r) * CH + c16 * 8);
        }
        CP_COMMIT();
    };

    issue(0, KVB);
    issue(1, KVB + KVBUF);
    CP_WAIT1();
    __syncthreads();

    for (int ct = 0; ct < 64; ++ct) {
        const uint32_t buf = KVB + (ct & 1) * KVBUF;
        const uint32_t KhS = buf, KlS = buf + KTPB, VhS = buf + 2 * KTPB, VlS = buf + 3 * KTPB;

        // ---- S = Q K^T (split-3), warp tile 32 x 64
        float S[2][8][4];
#pragma unroll
        for (int mf = 0; mf < 2; ++mf)
#pragma unroll
            for (int nf = 0; nf < 8; ++nf)
#pragma unroll
                for (int e = 0; e < 4; ++e) S[mf][nf][e] = 0.f;

#pragma unroll
        for (int ks = 0; ks < 6; ++ks) {
            uint32_t QH0[4], QH1[4], QL0[4], QL1[4], Bf[8][2];
            ldsm4(QH0, QhS + arowQ + ks * 32);
            ldsm4(QH1, QhS + arowQ + 16 * 208 + ks * 32);
            ldsm4(QL0, QlS + arowQ + ks * 32);
            ldsm4(QL1, QlS + arowQ + 16 * 208 + ks * 32);
#pragma unroll
            for (int p = 0; p < 4; ++p) {
                uint32_t r4[4];
                ldsm4(r4, KhS + bofsK4 + p * 16 * 208 + ks * 32);
                Bf[2 * p][0] = r4[0]; Bf[2 * p][1] = r4[1];
                Bf[2 * p + 1][0] = r4[2]; Bf[2 * p + 1][1] = r4[3];
            }
#pragma unroll
            for (int nf = 0; nf < 8; ++nf) {
                mma_bf16(S[0][nf], QH0, Bf[nf]);
                mma_bf16(S[1][nf], QH1, Bf[nf]);
            }
#pragma unroll
            for (int nf = 0; nf < 8; ++nf) {
                mma_bf16(S[0][nf], QL0, Bf[nf]);
                mma_bf16(S[1][nf], QL1, Bf[nf]);
            }
#pragma unroll
            for (int p = 0; p < 4; ++p) {
                uint32_t r4[4];
                ldsm4(r4, KlS + bofsK4 + p * 16 * 208 + ks * 32);
                Bf[2 * p][0] = r4[0]; Bf[2 * p][1] = r4[1];
                Bf[2 * p + 1][0] = r4[2]; Bf[2 * p + 1][1] = r4[3];
            }
#pragma unroll
            for (int nf = 0; nf < 8; ++nf) {
                mma_bf16(S[0][nf], QH0, Bf[nf]);
                mma_bf16(S[1][nf], QH1, Bf[nf]);
            }
        }

        // ---- online softmax per M-frag, vote-guarded rescale
#pragma unroll
        for (int mf = 0; mf < 2; ++mf) {
            float r0 = -1e30f, r1 = -1e30f;
#pragma unroll
            for (int nf = 0; nf < 8; ++nf) {
                r0 = fmaxf(r0, fmaxf(S[mf][nf][0], S[mf][nf][1]));
                r1 = fmaxf(r1, fmaxf(S[mf][nf][2], S[mf][nf][3]));
            }
            r0 = fmaxf(r0, __shfl_xor_sync(0xffffffffu, r0, 1));
            r0 = fmaxf(r0, __shfl_xor_sync(0xffffffffu, r0, 2));
            r1 = fmaxf(r1, __shfl_xor_sync(0xffffffffu, r1, 1));
            r1 = fmaxf(r1, __shfl_xor_sync(0xffffffffu, r1, 2));
            const float nm0 = fmaxf(m[2 * mf], r0), nm1 = fmaxf(m[2 * mf + 1], r1);
            const bool need = (nm0 > m[2 * mf]) || (nm1 > m[2 * mf + 1]);
            const uint32_t vote = __ballot_sync(0xffffffffu, need);
            float sc0 = 1.f, sc1 = 1.f;
            if (vote) {
                sc0 = fexp(m[2 * mf] - nm0);
                sc1 = fexp(m[2 * mf + 1] - nm1);
            }
            m[2 * mf] = nm0; m[2 * mf + 1] = nm1;

            float ps0 = 0.f, ps1 = 0.f;
#pragma unroll
            for (int nf = 0; nf < 8; ++nf) {
                S[mf][nf][0] = fexp(S[mf][nf][0] - nm0);
                S[mf][nf][1] = fexp(S[mf][nf][1] - nm0);
                S[mf][nf][2] = fexp(S[mf][nf][2] - nm1);
                S[mf][nf][3] = fexp(S[mf][nf][3] - nm1);
                ps0 += S[mf][nf][0] + S[mf][nf][1];
                ps1 += S[mf][nf][2] + S[mf][nf][3];
            }
            ps0 += __shfl_xor_sync(0xffffffffu, ps0, 1);
            ps0 += __shfl_xor_sync(0xffffffffu, ps0, 2);
            ps1 += __shfl_xor_sync(0xffffffffu, ps1, 1);
            ps1 += __shfl_xor_sync(0xffffffffu, ps1, 2);
            ls[2 * mf]     = ls[2 * mf] * sc0 + ps0;
            ls[2 * mf + 1] = ls[2 * mf + 1] * sc1 + ps1;
            if (vote) {
#pragma unroll
                for (int nf = 0; nf < 12; ++nf) {
                    O[mf][nf][0] *= sc0; O[mf][nf][1] *= sc0;
                    O[mf][nf][2] *= sc1; O[mf][nf][3] *= sc1;
                }
            }
        }

        // ---- O += P V (split-3): V fragments shared by both M-frags
#pragma unroll
        for (int ks = 0; ks < 4; ++ks) {
            uint32_t PH0[4], PL0[4], PH1[4], PL1[4];
            split2pack(S[0][2 * ks][0],     S[0][2 * ks][1],     PH0[0], PL0[0]);
            split2pack(S[0][2 * ks][2],     S[0][2 * ks][3],     PH0[1], PL0[1]);
            split2pack(S[0][2 * ks + 1][0], S[0][2 * ks + 1][1], PH0[2], PL0[2]);
            split2pack(S[0][2 * ks + 1][2], S[0][2 * ks + 1][3], PH0[3], PL0[3]);
            split2pack(S[1][2 * ks][0],     S[1][2 * ks][1],     PH1[0], PL1[0]);
            split2pack(S[1][2 * ks][2],     S[1][2 * ks][3],     PH1[1], PL1[1]);
            split2pack(S[1][2 * ks + 1][0], S[1][2 * ks + 1][1], PH1[2], PL1[2]);
            split2pack(S[1][2 * ks + 1][2], S[1][2 * ks + 1][3], PH1[3], PL1[3]);

            uint32_t Vf[12][2];
            const uint32_t vkr = ks * 16 * 208 + browV4;
#pragma unroll
            for (int p = 0; p < 6; ++p) {
                uint32_t r4[4];
                ldsm4t(r4, VhS + vkr + p * 32);
                Vf[2 * p][0] = r4[0]; Vf[2 * p][1] = r4[1];
                Vf[2 * p + 1][0] = r4[2]; Vf[2 * p + 1][1] = r4[3];
            }
#pragma unroll
            for (int nf = 0; nf < 12; ++nf) {
                mma_bf16(O[0][nf], PH0, Vf[nf]);
                mma_bf16(O[1][nf], PH1, Vf[nf]);
            }
#pragma unroll
            for (int nf = 0; nf < 12; ++nf) {
                mma_bf16(O[0][nf], PL0, Vf[nf]);
                mma_bf16(O[1][nf], PL1, Vf[nf]);
            }
#pragma unroll
            for (int p = 0; p < 6; ++p) {
                uint32_t r4[4];
                ldsm4t(r4, VlS + vkr + p * 32);
                Vf[2 * p][0] = r4[0]; Vf[2 * p][1] = r4[1];
                Vf[2 * p + 1][0] = r4[2]; Vf[2 * p + 1][1] = r4[3];
            }
#pragma unroll
            for (int nf = 0; nf < 12; ++nf) {
                mma_bf16(O[0][nf], PH0, Vf[nf]);
                mma_bf16(O[1][nf], PH1, Vf[nf]);
            }
        }

        __syncthreads();
        issue(ct + 2, buf);
        CP_WAIT1();
        __syncthreads();
    }

    // ---- epilogue: normalize, split, write g_Oh/g_Ol
#pragma unroll
    for (int mf = 0; mf < 2; ++mf) {
        const float i0 = 1.f / ls[2 * mf], i1 = 1.f / ls[2 * mf + 1];
        size_t rb = ((size_t)b * LSEQ + q0 + wid * 32 + mf * 16 + gr) * CH;
#pragma unroll
        for (int nf = 0; nf < 12; ++nf) {
            int col = nf * 8 + c2;
            uint32_t h, l;
            split2pack(O[mf][nf][0] * i0, O[mf][nf][1] * i0, h, l);
            *(uint32_t*)(g_Oh + rb + col) = h;
            *(uint32_t*)(g_Ol + rb + col) = l;
            split2pack(O[mf][nf][2] * i1, O[mf][nf][3] * i1, h, l);
            *(uint32_t*)(g_Oh + rb + 8 * CH + col) = h;
            *(uint32_t*)(g_Ol + rb + 8 * CH + col) = l;
        }
    }
}

// ============================================================================
// Kernel 3: y[b,o,l] = gamma * (Wlast . O) + x via split-bf16 MMA (unchanged).
// ============================================================================
#define OM_SMEM (2 * 128 * FAP * 2 + 2 * 96 * FAP * 2)

__global__ __launch_bounds__(256, 2) void outmma_kernel(
    const float* __restrict__ x,
    const float* __restrict__ gammap,
    float* __restrict__ out)
{
    extern __shared__ char smraw[];
    const uint32_t base = s2u(smraw);
    const uint32_t OhS = base, OlS = base + 26624, WhS = base + 53248, WlS = base + 73216;
    float* sst = (float*)smraw;

    const int l0 = blockIdx.x * 128;
    const int o0 = blockIdx.y * 96;
    const int b  = blockIdx.z;
    const int tid = threadIdx.x, wid = tid >> 5, lane = tid & 31;
    const int wm = wid & 1, wn = wid >> 1;
    const int gr = lane >> 2, c2 = (lane & 3) * 2;
    const float gamma = gammap[0];

    {
        const __nv_bfloat16* Oh = g_Oh + ((size_t)b * LSEQ + l0) * CH;
        const __nv_bfloat16* Ol = g_Ol + ((size_t)b * LSEQ + l0) * CH;
#pragma unroll
        for (int it = 0; it < 6; ++it) {
            int idx = tid + it * 256;
            int r = idx / 12, c16 = idx % 12;
            cpa16(OhS + r * 208 + c16 * 16, Oh + (size_t)r * CH + c16 * 8);
            cpa16(OlS + r * 208 + c16 * 16, Ol + (size_t)r * CH + c16 * 8);
        }
        const __nv_bfloat16* Wh = g_Wh + (size_t)o0 * CH;
        const __nv_bfloat16* Wl = g_Wl + (size_t)o0 * CH;
#pragma unroll
        for (int it = 0; it < 5; ++it) {
            int idx = tid + it * 256;
            if (idx < 1152) {
                int r = idx / 12, c16 = idx % 12;
                cpa16(WhS + r * 208 + c16 * 16, Wh + (size_t)r * CH + c16 * 8);
                cpa16(WlS + r * 208 + c16 * 16, Wl + (size_t)r * CH + c16 * 8);
            }
        }
        CP_COMMIT();
        CP_WAIT0();
    }
    __syncthreads();

    const uint32_t aoff = ((wm * 64 + (lane & 15)) * FAP + ((lane >> 4) << 3)) * 2;
    const uint32_t bofs = ((wn * 24 + (lane & 7)) * FAP + (((lane >> 3) & 1) << 3)) * 2;

    float D[4][3][4];
#pragma unroll
    for (int mf = 0; mf < 4; ++mf)
#pragma unroll
        for (int nf = 0; nf < 3; ++nf)
#pragma unroll
            for (int e = 0; e < 4; ++e) D[mf][nf][e] = 0.f;

#pragma unroll
    for (int ks = 0; ks < 6; ++ks) {
        uint32_t A[4][4], L[4][4], Bf[3][2];
#pragma unroll
        for (int mf = 0; mf < 4; ++mf)
            ldsm4(A[mf], OhS + aoff + mf * 16 * (FAP * 2) + ks * 32);
#pragma unroll
        for (int nf = 0; nf < 3; ++nf)
            ldsm2(Bf[nf], WhS + bofs + nf * 8 * (FAP * 2) + ks * 32);
#pragma unroll
        for (int mf = 0; mf < 4; ++mf)
#pragma unroll
            for (int nf = 0; nf < 3; ++nf) mma_bf16(D[mf][nf], A[mf], Bf[nf]);
#pragma unroll
        for (int mf = 0; mf < 4; ++mf)
            ldsm4(L[mf], OlS + aoff + mf * 16 * (FAP * 2) + ks * 32);
#pragma unroll
        for (int mf = 0; mf < 4; ++mf)
#pragma unroll
            for (int nf = 0; nf < 3; ++nf) mma_bf16(D[mf][nf], L[mf], Bf[nf]);
#pragma unroll
        for (int nf = 0; nf < 3; ++nf)
            ldsm2(Bf[nf], WlS + bofs + nf * 8 * (FAP * 2) + ks * 32);
#pragma unroll
        for (int mf = 0; mf < 4; ++mf)
#pragma unroll
            for (int nf = 0; nf < 3; ++nf) mma_bf16(D[mf][nf], A[mf], Bf[nf]);
    }
    __syncthreads();

#pragma unroll
    for (int mf = 0; mf < 4; ++mf) {
        int row = wm * 64 + mf * 16 + gr;
#pragma unroll
        for (int nf = 0; nf < 3; ++nf) {
            int col = wn * 24 + nf * 8 + c2;
            sst[(col)     * 132 + row]     = D[mf][nf][0];
            sst[(col + 1) * 132 + row]     = D[mf][nf][1];
            sst[(col)     * 132 + row + 8] = D[mf][nf][2];
            sst[(col + 1) * 132 + row + 8] = D[mf][nf][3];
        }
    }
    __syncthreads();

#pragma unroll
    for (int it = 0; it < 12; ++it) {
        int idx = tid + it * 256;
        int o = idx >> 5, l4 = idx & 31;
        float4 v = *(const float4*)&sst[o * 132 + l4 * 4];
        size_t gbase = (size_t)b * COUTC * LSEQ + (size_t)(o0 + o) * LSEQ + l0 + l4 * 4;
        float4 xr = *(const float4*)(x + gbase);
        *(float4*)(out + gbase) = make_float4(fmaf(gamma, v.x, xr.x),
                                              fmaf(gamma, v.y, xr.y),
                                              fmaf(gamma, v.z, xr.z),
                                              fmaf(gamma, v.w, xr.w));
    }
}

// ============================================================================
extern "C" void kernel_launch(void* const* d_in, const int* in_sizes, int n_in,
                              void* d_out, int out_size) {
    const float* x     = (const float*)d_in[0];
    const float* Wq    = (const float*)d_in[1];
    const float* Wk    = (const float*)d_in[2];
    const float* Wv    = (const float*)d_in[3];
    const float* Wl    = (const float*)d_in[4];
    const float* gamma = (const float*)d_in[5];
    float* out = (float*)d_out;

    cudaFuncSetAttribute(projmma_kernel, cudaFuncAttributeMaxDynamicSharedMemorySize, PJ_SMEM);
    cudaFuncSetAttribute(fattn_kernel,   cudaFuncAttributeMaxDynamicSharedMemorySize, FA_SMEM);
    cudaFuncSetAttribute(outmma_kernel,  cudaFuncAttributeMaxDynamicSharedMemorySize, OM_SMEM);

    wsplit_kernel<<<288, 256>>>(Wq, Wk, Wv, Wl);
    projmma_kernel<<<dim3(32, 1, 8), 256, PJ_SMEM>>>(x);
    fattn_kernel<<<dim3(16, 8), 256, FA_SMEM>>>();
    outmma_kernel<<<dim3(32, 8, 8), 256, OM_SMEM>>>(x, gamma, out);
}